// round 14
// baseline (speedup 1.0000x reference)
#include <cuda_runtime.h>
#include <cuda_fp16.h>
#include <math.h>

#define NNODES 50000
#define NEDGES 800000
#define EALL   850000          // edges + self loops
#define F_IN   32
#define CELL_DIM 16
#define D_IN   48              // F_IN + CELL_DIM
#define XCOLS  33              // F_IN + 1 (cell id column)
#define C      64
#define NEG_SLOPE 0.2f
#define OFFB   ((NNODES + 255) / 256)    // 196 offset blocks
#define NB0    8
#define T0B    ((NNODES + NB0 - 1) / NB0)     // 6250 transform0 blocks
#define FILLB  ((EALL + 127) / 128)           // 6641 fill blocks

// ---------------- scratch ----------------------------------------------------
__device__ int    g_deg[NNODES + 1];     // [NNODES] doubles as global cursor
__device__ int    g_off[NNODES];
__device__ int    g_cursor[NNODES];
__device__ int    g_csrc[EALL];
__device__ int    g_cdst[EALL];
__device__ float  g_p0[EALL * 2];        // edge softmax weights, csr order [h0,h1]
__device__ __half g_h0[NNODES * 128];    // layer0 transformed, fp16 [N, h0|h1]
__device__ float  g_as0[NNODES * 2];
__device__ float  g_ad0[NNODES * 2];
__device__ __half g_h1[NNODES * C];      // layer1 transformed, fp16
__device__ float  g_as1[NNODES];
__device__ float  g_ad1[NNODES];
__device__ float  g_ws0[D_IN * 2];       // W0 @ a_src0   [k][h]
__device__ float  g_wd0[D_IN * 2];       // W0 @ a_dst0   [k][h]

__device__ __forceinline__ float warpSum(float v) {
#pragma unroll
    for (int o = 16; o; o >>= 1) v += __shfl_xor_sync(0xffffffffu, v, o);
    return v;
}

__device__ __forceinline__ float lrelu(float e) {
    return e > 0.f ? e : NEG_SLOPE * e;
}

// ---------------- CSR: count -------------------------------------------------
__global__ void k_count(const int* __restrict__ ei) {
    int i = blockIdx.x * blockDim.x + threadIdx.x;
    if (i >= EALL) return;
    int d = (i < NEDGES) ? ei[NEDGES + i] : (i - NEDGES);
    atomicAdd(&g_deg[d], 1);
}

// Atomic segment assignment (order-independent); block OFFB additionally
// precomputes ws0/wd0 = W0 @ a_{src,dst}0.
__global__ void k_offsets(const float* __restrict__ W0,
                          const float* __restrict__ as0,
                          const float* __restrict__ ad0) {
    int b = blockIdx.x, tid = threadIdx.x;
    if (b < OFFB) {
        int i = b * 256 + tid;
        if (i >= NNODES) return;
        int d = g_deg[i];
        int o = atomicAdd(&g_deg[NNODES], d);
        g_off[i] = o;
        g_cursor[i] = o;
    } else if (tid < 192) {
        int idx = tid % 96, which = tid / 96;       // 96 = D_IN*2
        int k = idx >> 1, h = idx & 1;
        const float* a = which ? ad0 : as0;
        float s = 0.f;
#pragma unroll
        for (int c = 0; c < 64; c++)
            s = fmaf(W0[k * 128 + h * 64 + c], a[h * 64 + c], s);
        if (which) g_wd0[idx] = s; else g_ws0[idx] = s;
    }
}

// ---------------- fused: transform0 (blocks < T0B)  ||  CSR fill -------------
__global__ void __launch_bounds__(128) k_t0_fill(
        const int* __restrict__ ei,
        const float* __restrict__ x,
        const float* __restrict__ emb,
        const float* __restrict__ W0) {
    if (blockIdx.x >= T0B) {             // ---- fill branch ----
        int i = (blockIdx.x - T0B) * 128 + threadIdx.x;
        if (i >= EALL) return;
        int s, d;
        if (i < NEDGES) { s = ei[i]; d = ei[NEDGES + i]; }
        else            { s = i - NEDGES; d = s; }
        int p = atomicAdd(&g_cursor[d], 1);
        g_csrc[p] = s;
        g_cdst[p] = d;
        return;
    }
    // ---- transform0 branch ----
    __shared__ float sfeat[NB0][D_IN];   // [node-in-tile][k]
    int j = threadIdx.x;
    int base = blockIdx.x * NB0;

    for (int idx = j; idx < NB0 * D_IN; idx += 128) {
        int nn = idx / D_IN, k = idx - nn * D_IN;
        int node = base + nn;
        if (node < NNODES) {
            float v;
            if (k < F_IN) v = x[node * XCOLS + k];
            else {
                int cid = (int)x[node * XCOLS + F_IN];
                v = emb[cid * CELL_DIM + (k - F_IN)];
            }
            sfeat[nn][k] = v;
        }
    }

    float w[D_IN];
#pragma unroll
    for (int k = 0; k < D_IN; k++) w[k] = W0[k * 128 + j];
    __syncthreads();

    float acc[NB0];
#pragma unroll
    for (int nn = 0; nn < NB0; nn++) acc[nn] = 0.f;
#pragma unroll
    for (int k = 0; k < D_IN; k++) {
        acc[0] = fmaf(sfeat[0][k], w[k], acc[0]);
        acc[1] = fmaf(sfeat[1][k], w[k], acc[1]);
        acc[2] = fmaf(sfeat[2][k], w[k], acc[2]);
        acc[3] = fmaf(sfeat[3][k], w[k], acc[3]);
        acc[4] = fmaf(sfeat[4][k], w[k], acc[4]);
        acc[5] = fmaf(sfeat[5][k], w[k], acc[5]);
        acc[6] = fmaf(sfeat[6][k], w[k], acc[6]);
        acc[7] = fmaf(sfeat[7][k], w[k], acc[7]);
    }
#pragma unroll
    for (int nn = 0; nn < NB0; nn++) {
        int node = base + nn;
        if (node < NNODES) g_h0[node * 128 + j] = __float2half_rn(acc[nn]);
    }
    // logits: 16 threads, one (node, head) each; fp32 throughout
    if (j < 2 * NB0) {
        int nn = j >> 1, h = j & 1;
        int node = base + nn;
        float as = 0.f, ad = 0.f;
#pragma unroll
        for (int k = 0; k < D_IN; k++) {
            float f = sfeat[nn][k];
            as = fmaf(f, g_ws0[k * 2 + h], as);
            ad = fmaf(f, g_wd0[k * 2 + h], ad);
        }
        if (node < NNODES) {
            g_as0[node * 2 + h] = as;
            g_ad0[node * 2 + h] = ad;
        }
    }
}

// ---------------- edge weights for layer0 (after transform0 + fill) ----------
__global__ void k_edge0() {
    int i = blockIdx.x * blockDim.x + threadIdx.x;
    if (i >= EALL) return;
    int s = g_csrc[i], d = g_cdst[i];
    float2 as = ((const float2*)g_as0)[s];
    float2 ad = ((const float2*)g_ad0)[d];
    float2 p;
    p.x = __expf(lrelu(as.x + ad.x));
    p.y = __expf(lrelu(as.y + ad.y));
    ((float2*)g_p0)[i] = p;
}

// ---------------- layer0 aggregation + LN/ELU + fused layer1 transform -------
// One warp per dst node, 8 warps/block. Lane L owns channels 4L..4L+3 of the
// 128-wide [head0|head1] row. Weights precomputed (broadcast loads); 4 chains.
__global__ void __launch_bounds__(256) k_agg0(
        const float* __restrict__ b0,
        const float* __restrict__ lng,
        const float* __restrict__ lnb,
        const float* __restrict__ W1,
        const float* __restrict__ a_s1,
        const float* __restrict__ a_d1) {
    __shared__ float sW1[64 * 64];       // 16 KB
    __shared__ float sa1[64], sd1[64];
    __shared__ float sy[8][64];
    int tid = threadIdx.x;
    for (int i = tid; i < 4096; i += 256) sW1[i] = W1[i];
    if (tid < 64) { sa1[tid] = a_s1[tid]; sd1[tid] = a_d1[tid]; }
    __syncthreads();

    int warp = tid >> 5, lane = tid & 31;
    int n = blockIdx.x * 8 + warp;
    if (n >= NNODES) return;

    int head = lane >> 4;
    int c4 = lane & 15;
    const float2* p0v = (const float2*)g_p0;
    const uint2* h0v = (const uint2*)g_h0;      // 4 halves per lane
    int p0 = g_off[n], p1 = p0 + g_deg[n];

    float s0 = 0.f, s1 = 0.f, s2 = 0.f, s3 = 0.f;
    float4 A0 = make_float4(0.f, 0.f, 0.f, 0.f);
    float4 A1 = make_float4(0.f, 0.f, 0.f, 0.f);
    float4 A2 = make_float4(0.f, 0.f, 0.f, 0.f);
    float4 A3 = make_float4(0.f, 0.f, 0.f, 0.f);

    for (int base = p0; base < p1; base += 32) {
        int cnt = min(32, p1 - base);
        int srcs = (lane < cnt) ? g_csrc[base + lane] : 0;
        int k = 0;
        for (; k + 3 < cnt; k += 4) {
            int sa = __shfl_sync(0xffffffffu, srcs, k);
            int sb = __shfl_sync(0xffffffffu, srcs, k + 1);
            int sc = __shfl_sync(0xffffffffu, srcs, k + 2);
            int sd = __shfl_sync(0xffffffffu, srcs, k + 3);
            float2 q0 = p0v[base + k];          // broadcast (all lanes same)
            float2 q1 = p0v[base + k + 1];
            float2 q2 = p0v[base + k + 2];
            float2 q3 = p0v[base + k + 3];
            uint2 r0 = h0v[sa * 32 + lane];
            uint2 r1 = h0v[sb * 32 + lane];
            uint2 r2 = h0v[sc * 32 + lane];
            uint2 r3 = h0v[sd * 32 + lane];
            float w0 = head ? q0.y : q0.x;
            float w1 = head ? q1.y : q1.x;
            float w2 = head ? q2.y : q2.x;
            float w3 = head ? q3.y : q3.x;
            float2 a01 = __half22float2(*(const __half2*)&r0.x);
            float2 a23 = __half22float2(*(const __half2*)&r0.y);
            float2 b01 = __half22float2(*(const __half2*)&r1.x);
            float2 b23 = __half22float2(*(const __half2*)&r1.y);
            float2 c01 = __half22float2(*(const __half2*)&r2.x);
            float2 c23 = __half22float2(*(const __half2*)&r2.y);
            float2 d01 = __half22float2(*(const __half2*)&r3.x);
            float2 d23 = __half22float2(*(const __half2*)&r3.y);
            s0 += w0; s1 += w1; s2 += w2; s3 += w3;
            A0.x = fmaf(w0, a01.x, A0.x); A0.y = fmaf(w0, a01.y, A0.y);
            A0.z = fmaf(w0, a23.x, A0.z); A0.w = fmaf(w0, a23.y, A0.w);
            A1.x = fmaf(w1, b01.x, A1.x); A1.y = fmaf(w1, b01.y, A1.y);
            A1.z = fmaf(w1, b23.x, A1.z); A1.w = fmaf(w1, b23.y, A1.w);
            A2.x = fmaf(w2, c01.x, A2.x); A2.y = fmaf(w2, c01.y, A2.y);
            A2.z = fmaf(w2, c23.x, A2.z); A2.w = fmaf(w2, c23.y, A2.w);
            A3.x = fmaf(w3, d01.x, A3.x); A3.y = fmaf(w3, d01.y, A3.y);
            A3.z = fmaf(w3, d23.x, A3.z); A3.w = fmaf(w3, d23.y, A3.w);
        }
        for (; k < cnt; k++) {
            int sa = __shfl_sync(0xffffffffu, srcs, k);
            float2 q0 = p0v[base + k];
            uint2 r0 = h0v[sa * 32 + lane];
            float w0 = head ? q0.y : q0.x;
            float2 a01 = __half22float2(*(const __half2*)&r0.x);
            float2 a23 = __half22float2(*(const __half2*)&r0.y);
            s0 += w0;
            A0.x = fmaf(w0, a01.x, A0.x); A0.y = fmaf(w0, a01.y, A0.y);
            A0.z = fmaf(w0, a23.x, A0.z); A0.w = fmaf(w0, a23.y, A0.w);
        }
    }
    float inv = 1.f / ((s0 + s1) + (s2 + s3));
    float4 r;
    r.x = ((A0.x + A1.x) + (A2.x + A3.x)) * inv;
    r.y = ((A0.y + A1.y) + (A2.y + A3.y)) * inv;
    r.z = ((A0.z + A1.z) + (A2.z + A3.z)) * inv;
    r.w = ((A0.w + A1.w) + (A2.w + A3.w)) * inv;

    // head mean across halves, + bias
    float4 o;
    o.x = __shfl_xor_sync(0xffffffffu, r.x, 16);
    o.y = __shfl_xor_sync(0xffffffffu, r.y, 16);
    o.z = __shfl_xor_sync(0xffffffffu, r.z, 16);
    o.w = __shfl_xor_sync(0xffffffffu, r.w, 16);
    float4 bv = ((const float4*)b0)[c4];
    float4 v;
    v.x = 0.5f * (r.x + o.x) + bv.x;
    v.y = 0.5f * (r.y + o.y) + bv.y;
    v.z = 0.5f * (r.z + o.z) + bv.z;
    v.w = 0.5f * (r.w + o.w) + bv.w;

    // LayerNorm (each channel appears twice across the warp)
    float mu = warpSum(v.x + v.y + v.z + v.w) * (1.f / 128.f);
    float4 d = make_float4(v.x - mu, v.y - mu, v.z - mu, v.w - mu);
    float var = warpSum(d.x * d.x + d.y * d.y + d.z * d.z + d.w * d.w) * (1.f / 128.f);
    float rsv = rsqrtf(var + 1e-5f);
    float4 gv = ((const float4*)lng)[c4];
    float4 bb = ((const float4*)lnb)[c4];
    float4 y;
    y.x = d.x * rsv * gv.x + bb.x;
    y.y = d.y * rsv * gv.y + bb.y;
    y.z = d.z * rsv * gv.z + bb.z;
    y.w = d.w * rsv * gv.w + bb.w;
    // ELU via fast exp (abs err ~1e-7, fine vs expm1)
    y.x = y.x > 0.f ? y.x : (__expf(y.x) - 1.f);
    y.y = y.y > 0.f ? y.y : (__expf(y.y) - 1.f);
    y.z = y.z > 0.f ? y.z : (__expf(y.z) - 1.f);
    y.w = y.w > 0.f ? y.w : (__expf(y.w) - 1.f);

    // stage y[64] for this warp's node
    if (lane < 16) ((float4*)sy[warp])[c4] = y;
    __syncwarp();

    // fused layer1 transform: h1 = y @ W1; lane computes columns 2L, 2L+1
    float a0 = 0.f, a1 = 0.f;
#pragma unroll
    for (int k4 = 0; k4 < 16; k4++) {
        float4 y4 = ((const float4*)sy[warp])[k4];
        float2 w0 = ((const float2*)(sW1 + (4 * k4 + 0) * 64))[lane];
        float2 w1 = ((const float2*)(sW1 + (4 * k4 + 1) * 64))[lane];
        float2 w2 = ((const float2*)(sW1 + (4 * k4 + 2) * 64))[lane];
        float2 w3 = ((const float2*)(sW1 + (4 * k4 + 3) * 64))[lane];
        a0 = fmaf(y4.x, w0.x, a0); a1 = fmaf(y4.x, w0.y, a1);
        a0 = fmaf(y4.y, w1.x, a0); a1 = fmaf(y4.y, w1.y, a1);
        a0 = fmaf(y4.z, w2.x, a0); a1 = fmaf(y4.z, w2.y, a1);
        a0 = fmaf(y4.w, w3.x, a0); a1 = fmaf(y4.w, w3.y, a1);
    }
    ((__half2*)g_h1)[n * 32 + lane] = __floats2half2_rn(a0, a1);
    float ts = warpSum(a0 * sa1[2 * lane] + a1 * sa1[2 * lane + 1]);
    float td = warpSum(a0 * sd1[2 * lane] + a1 * sd1[2 * lane + 1]);
    if (lane == 0) { g_as1[n] = ts; g_ad1[n] = td; }
}

// ---------------- layer1 aggregation -> output -------------------------------
// One warp per dst node, lane owns channels 2L..2L+1 (half2 gather), 2 chains.
__global__ void __launch_bounds__(256) k_agg1(const float* __restrict__ b1,
                                              float* __restrict__ out) {
    int tid = threadIdx.x;
    int warp = tid >> 5, lane = tid & 31;
    int n = blockIdx.x * 8 + warp;
    if (n >= NNODES) return;
    float add = g_ad1[n];
    int p0 = g_off[n], p1 = p0 + g_deg[n];
    const __half2* h1v = (const __half2*)g_h1;

    float sP = 0.f, sQ = 0.f;
    float2 accP = make_float2(0.f, 0.f);
    float2 accQ = make_float2(0.f, 0.f);

    for (int base = p0; base < p1; base += 32) {
        int cnt = min(32, p1 - base);
        int srcs = (lane < cnt) ? g_csrc[base + lane] : 0;
        int k = 0;
        for (; k + 1 < cnt; k += 2) {
            int sa = __shfl_sync(0xffffffffu, srcs, k);
            int sb = __shfl_sync(0xffffffffu, srcs, k + 1);
            float pa = __expf(lrelu(g_as1[sa] + add));
            float pb = __expf(lrelu(g_as1[sb] + add));
            float2 ha = __half22float2(h1v[sa * 32 + lane]);
            float2 hb = __half22float2(h1v[sb * 32 + lane]);
            sP += pa; sQ += pb;
            accP.x = fmaf(pa, ha.x, accP.x);
            accP.y = fmaf(pa, ha.y, accP.y);
            accQ.x = fmaf(pb, hb.x, accQ.x);
            accQ.y = fmaf(pb, hb.y, accQ.y);
        }
        if (k < cnt) {
            int sa = __shfl_sync(0xffffffffu, srcs, k);
            float pa = __expf(lrelu(g_as1[sa] + add));
            float2 ha = __half22float2(h1v[sa * 32 + lane]);
            sP += pa;
            accP.x = fmaf(pa, ha.x, accP.x);
            accP.y = fmaf(pa, ha.y, accP.y);
        }
    }
    float inv = 1.f / (sP + sQ);
    float2 bv = ((const float2*)b1)[lane];
    float2 o;
    o.x = (accP.x + accQ.x) * inv + bv.x;
    o.y = (accP.y + accQ.y) * inv + bv.y;
    ((float2*)(out + n * 64))[lane] = o;
}

// ---------------- launch -----------------------------------------------------
extern "C" void kernel_launch(void* const* d_in, const int* in_sizes, int n_in,
                              void* d_out, int out_size) {
    const float* x   = (const float*)d_in[0];
    const int*   ei  = (const int*)  d_in[1];
    const float* emb = (const float*)d_in[2];
    const float* W0  = (const float*)d_in[3];
    const float* as0 = (const float*)d_in[4];
    const float* ad0 = (const float*)d_in[5];
    const float* b0  = (const float*)d_in[6];
    const float* lng = (const float*)d_in[7];
    const float* lnb = (const float*)d_in[8];
    const float* W1  = (const float*)d_in[9];
    const float* as1 = (const float*)d_in[10];
    const float* ad1 = (const float*)d_in[11];
    const float* b1  = (const float*)d_in[12];
    float* out = (float*)d_out;

    void* degPtr = nullptr;
    cudaGetSymbolAddress(&degPtr, g_deg);
    cudaMemsetAsync(degPtr, 0, (NNODES + 1) * sizeof(int));

    k_count<<<(EALL + 255) / 256, 256>>>(ei);
    k_offsets<<<OFFB + 1, 256>>>(W0, as0, ad0);
    k_t0_fill<<<T0B + FILLB, 128>>>(ei, x, emb, W0);
    k_edge0<<<(EALL + 255) / 256, 256>>>();
    k_agg0<<<(NNODES + 7) / 8, 256>>>(b0, lng, lnb, W1, as1, ad1);
    k_agg1<<<(NNODES + 7) / 8, 256>>>(b1, out);
}

// round 15
// speedup vs baseline: 1.0220x; 1.0220x over previous
#include <cuda_runtime.h>
#include <cuda_fp16.h>
#include <math.h>

#define NNODES 50000
#define NEDGES 800000
#define EALL   850000          // edges + self loops
#define F_IN   32
#define CELL_DIM 16
#define D_IN   48              // F_IN + CELL_DIM
#define XCOLS  33              // F_IN + 1 (cell id column)
#define C      64
#define NEG_SLOPE 0.2f
#define OFFB   ((NNODES + 255) / 256)    // 196 offset blocks
#define NB0    8
#define T0B    ((NNODES + NB0 - 1) / NB0)     // 6250 transform0 blocks
#define FILLB  ((EALL + 127) / 128)           // 6641 fill blocks

// ---------------- scratch ----------------------------------------------------
__device__ int    g_deg[NNODES + 1];     // [NNODES] doubles as global cursor
__device__ int    g_off[NNODES];
__device__ int    g_cursor[NNODES];
__device__ int    g_csrc[EALL];
__device__ float  g_h0[NNODES * 128];    // layer0 transformed, fp32 [N, h0|h1]
__device__ float  g_as0[NNODES * 2];
__device__ float  g_ad0[NNODES * 2];
__device__ __half g_h1[NNODES * C];      // layer1 transformed, fp16
__device__ float  g_as1[NNODES];
__device__ float  g_ad1[NNODES];
__device__ float  g_ws0[D_IN * 2];       // W0 @ a_src0   [k][h]
__device__ float  g_wd0[D_IN * 2];       // W0 @ a_dst0   [k][h]

__device__ __forceinline__ float warpSum(float v) {
#pragma unroll
    for (int o = 16; o; o >>= 1) v += __shfl_xor_sync(0xffffffffu, v, o);
    return v;
}

__device__ __forceinline__ float lrelu(float e) {
    return e > 0.f ? e : NEG_SLOPE * e;
}

// ---------------- CSR: count -------------------------------------------------
__global__ void k_count(const int* __restrict__ ei) {
    int i = blockIdx.x * blockDim.x + threadIdx.x;
    if (i >= EALL) return;
    int d = (i < NEDGES) ? ei[NEDGES + i] : (i - NEDGES);
    atomicAdd(&g_deg[d], 1);
}

// Atomic segment assignment (order-independent); block OFFB additionally
// precomputes ws0/wd0 = W0 @ a_{src,dst}0.
__global__ void k_offsets(const float* __restrict__ W0,
                          const float* __restrict__ as0,
                          const float* __restrict__ ad0) {
    int b = blockIdx.x, tid = threadIdx.x;
    if (b < OFFB) {
        int i = b * 256 + tid;
        if (i >= NNODES) return;
        int d = g_deg[i];
        int o = atomicAdd(&g_deg[NNODES], d);
        g_off[i] = o;
        g_cursor[i] = o;
    } else if (tid < 192) {
        int idx = tid % 96, which = tid / 96;       // 96 = D_IN*2
        int k = idx >> 1, h = idx & 1;
        const float* a = which ? ad0 : as0;
        float s = 0.f;
#pragma unroll
        for (int c = 0; c < 64; c++)
            s = fmaf(W0[k * 128 + h * 64 + c], a[h * 64 + c], s);
        if (which) g_wd0[idx] = s; else g_ws0[idx] = s;
    }
}

// ---------------- fused: transform0 (blocks < T0B)  ||  CSR fill -------------
__global__ void __launch_bounds__(128) k_t0_fill(
        const int* __restrict__ ei,
        const float* __restrict__ x,
        const float* __restrict__ emb,
        const float* __restrict__ W0) {
    if (blockIdx.x >= T0B) {             // ---- fill branch ----
        int i = (blockIdx.x - T0B) * 128 + threadIdx.x;
        if (i >= EALL) return;
        int s, d;
        if (i < NEDGES) { s = ei[i]; d = ei[NEDGES + i]; }
        else            { s = i - NEDGES; d = s; }
        int p = atomicAdd(&g_cursor[d], 1);
        g_csrc[p] = s;
        return;
    }
    // ---- transform0 branch ----
    __shared__ float sfeat[NB0][D_IN];   // [node-in-tile][k]
    int j = threadIdx.x;
    int base = blockIdx.x * NB0;

    for (int idx = j; idx < NB0 * D_IN; idx += 128) {
        int nn = idx / D_IN, k = idx - nn * D_IN;
        int node = base + nn;
        if (node < NNODES) {
            float v;
            if (k < F_IN) v = x[node * XCOLS + k];
            else {
                int cid = (int)x[node * XCOLS + F_IN];
                v = emb[cid * CELL_DIM + (k - F_IN)];
            }
            sfeat[nn][k] = v;
        }
    }

    float w[D_IN];
#pragma unroll
    for (int k = 0; k < D_IN; k++) w[k] = W0[k * 128 + j];
    __syncthreads();

    float acc[NB0];
#pragma unroll
    for (int nn = 0; nn < NB0; nn++) acc[nn] = 0.f;
#pragma unroll
    for (int k = 0; k < D_IN; k++) {
        acc[0] = fmaf(sfeat[0][k], w[k], acc[0]);
        acc[1] = fmaf(sfeat[1][k], w[k], acc[1]);
        acc[2] = fmaf(sfeat[2][k], w[k], acc[2]);
        acc[3] = fmaf(sfeat[3][k], w[k], acc[3]);
        acc[4] = fmaf(sfeat[4][k], w[k], acc[4]);
        acc[5] = fmaf(sfeat[5][k], w[k], acc[5]);
        acc[6] = fmaf(sfeat[6][k], w[k], acc[6]);
        acc[7] = fmaf(sfeat[7][k], w[k], acc[7]);
    }
#pragma unroll
    for (int nn = 0; nn < NB0; nn++) {
        int node = base + nn;
        if (node < NNODES) g_h0[node * 128 + j] = acc[nn];
    }
    // logits: 16 threads, one (node, head) each; fp32 throughout
    if (j < 2 * NB0) {
        int nn = j >> 1, h = j & 1;
        int node = base + nn;
        float as = 0.f, ad = 0.f;
#pragma unroll
        for (int k = 0; k < D_IN; k++) {
            float f = sfeat[nn][k];
            as = fmaf(f, g_ws0[k * 2 + h], as);
            ad = fmaf(f, g_wd0[k * 2 + h], ad);
        }
        if (node < NNODES) {
            g_as0[node * 2 + h] = as;
            g_ad0[node * 2 + h] = ad;
        }
    }
}

// ---------------- layer0 aggregation + LN/ELU + fused layer1 transform -------
// One warp per dst node, 8 warps/block. Lane L owns channels 4L..4L+3 of the
// 128-wide [head0|head1] row (lanes 0-15 head0, 16-31 head1). fp32 gather
// (no converts — agg0 is issue-bound, not bandwidth-bound). 2 chains.
__global__ void __launch_bounds__(256) k_agg0(
        const float* __restrict__ b0,
        const float* __restrict__ lng,
        const float* __restrict__ lnb,
        const float* __restrict__ W1,
        const float* __restrict__ a_s1,
        const float* __restrict__ a_d1) {
    __shared__ float sW1[64 * 64];       // 16 KB
    __shared__ float sa1[64], sd1[64];
    __shared__ float sy[8][64];
    int tid = threadIdx.x;
    for (int i = tid; i < 4096; i += 256) sW1[i] = W1[i];
    if (tid < 64) { sa1[tid] = a_s1[tid]; sd1[tid] = a_d1[tid]; }
    __syncthreads();

    int warp = tid >> 5, lane = tid & 31;
    int n = blockIdx.x * 8 + warp;
    if (n >= NNODES) return;

    const float2* as0v = (const float2*)g_as0;
    const float2 adv = ((const float2*)g_ad0)[n];
    int head = lane >> 4;
    int c4 = lane & 15;
    int p0 = g_off[n], p1 = p0 + g_deg[n];

    float sP = 0.f, sQ = 0.f;
    float4 accP = make_float4(0.f, 0.f, 0.f, 0.f);
    float4 accQ = make_float4(0.f, 0.f, 0.f, 0.f);

    for (int base = p0; base < p1; base += 32) {
        int cnt = min(32, p1 - base);
        int srcs = (lane < cnt) ? g_csrc[base + lane] : 0;
        int k = 0;
        for (; k + 1 < cnt; k += 2) {
            int sa = __shfl_sync(0xffffffffu, srcs, k);
            int sb = __shfl_sync(0xffffffffu, srcs, k + 1);
            float2 asa = as0v[sa];
            float2 asb = as0v[sb];
            float4 ha = *(const float4*)(g_h0 + sa * 128 + lane * 4);
            float4 hb = *(const float4*)(g_h0 + sb * 128 + lane * 4);
            float pa = __expf(lrelu(head ? (asa.y + adv.y) : (asa.x + adv.x)));
            float pb = __expf(lrelu(head ? (asb.y + adv.y) : (asb.x + adv.x)));
            sP += pa; sQ += pb;
            accP.x = fmaf(pa, ha.x, accP.x);
            accP.y = fmaf(pa, ha.y, accP.y);
            accP.z = fmaf(pa, ha.z, accP.z);
            accP.w = fmaf(pa, ha.w, accP.w);
            accQ.x = fmaf(pb, hb.x, accQ.x);
            accQ.y = fmaf(pb, hb.y, accQ.y);
            accQ.z = fmaf(pb, hb.z, accQ.z);
            accQ.w = fmaf(pb, hb.w, accQ.w);
        }
        if (k < cnt) {
            int sa = __shfl_sync(0xffffffffu, srcs, k);
            float2 asa = as0v[sa];
            float4 ha = *(const float4*)(g_h0 + sa * 128 + lane * 4);
            float pa = __expf(lrelu(head ? (asa.y + adv.y) : (asa.x + adv.x)));
            sP += pa;
            accP.x = fmaf(pa, ha.x, accP.x);
            accP.y = fmaf(pa, ha.y, accP.y);
            accP.z = fmaf(pa, ha.z, accP.z);
            accP.w = fmaf(pa, ha.w, accP.w);
        }
    }
    float inv = 1.f / (sP + sQ);
    float4 r;
    r.x = (accP.x + accQ.x) * inv;
    r.y = (accP.y + accQ.y) * inv;
    r.z = (accP.z + accQ.z) * inv;
    r.w = (accP.w + accQ.w) * inv;

    // head mean across halves, + bias
    float4 o;
    o.x = __shfl_xor_sync(0xffffffffu, r.x, 16);
    o.y = __shfl_xor_sync(0xffffffffu, r.y, 16);
    o.z = __shfl_xor_sync(0xffffffffu, r.z, 16);
    o.w = __shfl_xor_sync(0xffffffffu, r.w, 16);
    float4 bv = ((const float4*)b0)[c4];
    float4 v;
    v.x = 0.5f * (r.x + o.x) + bv.x;
    v.y = 0.5f * (r.y + o.y) + bv.y;
    v.z = 0.5f * (r.z + o.z) + bv.z;
    v.w = 0.5f * (r.w + o.w) + bv.w;

    // LayerNorm (each channel appears twice across the warp)
    float mu = warpSum(v.x + v.y + v.z + v.w) * (1.f / 128.f);
    float4 d = make_float4(v.x - mu, v.y - mu, v.z - mu, v.w - mu);
    float var = warpSum(d.x * d.x + d.y * d.y + d.z * d.z + d.w * d.w) * (1.f / 128.f);
    float rsv = rsqrtf(var + 1e-5f);
    float4 gv = ((const float4*)lng)[c4];
    float4 bb = ((const float4*)lnb)[c4];
    float4 y;
    y.x = d.x * rsv * gv.x + bb.x;
    y.y = d.y * rsv * gv.y + bb.y;
    y.z = d.z * rsv * gv.z + bb.z;
    y.w = d.w * rsv * gv.w + bb.w;
    // ELU via fast exp (abs err ~1e-7 vs expm1)
    y.x = y.x > 0.f ? y.x : (__expf(y.x) - 1.f);
    y.y = y.y > 0.f ? y.y : (__expf(y.y) - 1.f);
    y.z = y.z > 0.f ? y.z : (__expf(y.z) - 1.f);
    y.w = y.w > 0.f ? y.w : (__expf(y.w) - 1.f);

    // stage y[64] for this warp's node
    if (lane < 16) ((float4*)sy[warp])[c4] = y;
    __syncwarp();

    // fused layer1 transform: h1 = y @ W1; lane computes columns 2L, 2L+1
    float a0 = 0.f, a1 = 0.f;
#pragma unroll
    for (int k4 = 0; k4 < 16; k4++) {
        float4 y4 = ((const float4*)sy[warp])[k4];
        float2 w0 = ((const float2*)(sW1 + (4 * k4 + 0) * 64))[lane];
        float2 w1 = ((const float2*)(sW1 + (4 * k4 + 1) * 64))[lane];
        float2 w2 = ((const float2*)(sW1 + (4 * k4 + 2) * 64))[lane];
        float2 w3 = ((const float2*)(sW1 + (4 * k4 + 3) * 64))[lane];
        a0 = fmaf(y4.x, w0.x, a0); a1 = fmaf(y4.x, w0.y, a1);
        a0 = fmaf(y4.y, w1.x, a0); a1 = fmaf(y4.y, w1.y, a1);
        a0 = fmaf(y4.z, w2.x, a0); a1 = fmaf(y4.z, w2.y, a1);
        a0 = fmaf(y4.w, w3.x, a0); a1 = fmaf(y4.w, w3.y, a1);
    }
    ((__half2*)g_h1)[n * 32 + lane] = __floats2half2_rn(a0, a1);
    float ts = warpSum(a0 * sa1[2 * lane] + a1 * sa1[2 * lane + 1]);
    float td = warpSum(a0 * sd1[2 * lane] + a1 * sd1[2 * lane + 1]);
    if (lane == 0) { g_as1[n] = ts; g_ad1[n] = td; }
}

// ---------------- layer1 aggregation -> output -------------------------------
// One warp per dst node, lane owns channels 2L..2L+1 (half2 gather), 2 chains.
__global__ void __launch_bounds__(256) k_agg1(const float* __restrict__ b1,
                                              float* __restrict__ out) {
    int tid = threadIdx.x;
    int warp = tid >> 5, lane = tid & 31;
    int n = blockIdx.x * 8 + warp;
    if (n >= NNODES) return;
    float add = g_ad1[n];
    int p0 = g_off[n], p1 = p0 + g_deg[n];
    const __half2* h1v = (const __half2*)g_h1;

    float sP = 0.f, sQ = 0.f;
    float2 accP = make_float2(0.f, 0.f);
    float2 accQ = make_float2(0.f, 0.f);

    for (int base = p0; base < p1; base += 32) {
        int cnt = min(32, p1 - base);
        int srcs = (lane < cnt) ? g_csrc[base + lane] : 0;
        int k = 0;
        for (; k + 1 < cnt; k += 2) {
            int sa = __shfl_sync(0xffffffffu, srcs, k);
            int sb = __shfl_sync(0xffffffffu, srcs, k + 1);
            float pa = __expf(lrelu(g_as1[sa] + add));
            float pb = __expf(lrelu(g_as1[sb] + add));
            float2 ha = __half22float2(h1v[sa * 32 + lane]);
            float2 hb = __half22float2(h1v[sb * 32 + lane]);
            sP += pa; sQ += pb;
            accP.x = fmaf(pa, ha.x, accP.x);
            accP.y = fmaf(pa, ha.y, accP.y);
            accQ.x = fmaf(pb, hb.x, accQ.x);
            accQ.y = fmaf(pb, hb.y, accQ.y);
        }
        if (k < cnt) {
            int sa = __shfl_sync(0xffffffffu, srcs, k);
            float pa = __expf(lrelu(g_as1[sa] + add));
            float2 ha = __half22float2(h1v[sa * 32 + lane]);
            sP += pa;
            accP.x = fmaf(pa, ha.x, accP.x);
            accP.y = fmaf(pa, ha.y, accP.y);
        }
    }
    float inv = 1.f / (sP + sQ);
    float2 bv = ((const float2*)b1)[lane];
    float2 o;
    o.x = (accP.x + accQ.x) * inv + bv.x;
    o.y = (accP.y + accQ.y) * inv + bv.y;
    ((float2*)(out + n * 64))[lane] = o;
}

// ---------------- launch -----------------------------------------------------
extern "C" void kernel_launch(void* const* d_in, const int* in_sizes, int n_in,
                              void* d_out, int out_size) {
    const float* x   = (const float*)d_in[0];
    const int*   ei  = (const int*)  d_in[1];
    const float* emb = (const float*)d_in[2];
    const float* W0  = (const float*)d_in[3];
    const float* as0 = (const float*)d_in[4];
    const float* ad0 = (const float*)d_in[5];
    const float* b0  = (const float*)d_in[6];
    const float* lng = (const float*)d_in[7];
    const float* lnb = (const float*)d_in[8];
    const float* W1  = (const float*)d_in[9];
    const float* as1 = (const float*)d_in[10];
    const float* ad1 = (const float*)d_in[11];
    const float* b1  = (const float*)d_in[12];
    float* out = (float*)d_out;

    void* degPtr = nullptr;
    cudaGetSymbolAddress(&degPtr, g_deg);
    cudaMemsetAsync(degPtr, 0, (NNODES + 1) * sizeof(int));

    k_count<<<(EALL + 255) / 256, 256>>>(ei);
    k_offsets<<<OFFB + 1, 256>>>(W0, as0, ad0);
    k_t0_fill<<<T0B + FILLB, 128>>>(ei, x, emb, W0);
    k_agg0<<<(NNODES + 7) / 8, 256>>>(b0, lng, lnb, W1, as1, ad1);
    k_agg1<<<(NNODES + 7) / 8, 256>>>(b1, out);
}

// round 16
// speedup vs baseline: 1.0911x; 1.0675x over previous
#include <cuda_runtime.h>
#include <cuda_fp16.h>
#include <math.h>

#define NNODES 50000
#define NEDGES 800000
#define EALL   850000          // edges + self loops
#define F_IN   32
#define CELL_DIM 16
#define D_IN   48              // F_IN + CELL_DIM
#define XCOLS  33              // F_IN + 1 (cell id column)
#define C      64
#define NEG_SLOPE 0.2f
#define OFFB   ((NNODES + 255) / 256)    // 196 offset blocks
#define NB0    8
#define T0B    ((NNODES + NB0 - 1) / NB0)     // 6250 transform0 blocks
#define FILLB  ((EALL + 127) / 128)           // 6641 fill blocks

// ---------------- scratch ----------------------------------------------------
__device__ int    g_deg[NNODES + 1];     // [NNODES] doubles as global cursor
__device__ int    g_off[NNODES];
__device__ int    g_cursor[NNODES];
__device__ int    g_csrc[EALL];
__device__ __half g_h0[NNODES * 128];    // layer0 transformed, fp16 [N, h0|h1]
__device__ float  g_as0[NNODES * 2];
__device__ float  g_ad0[NNODES * 2];
__device__ __half g_h1[NNODES * C];      // layer1 transformed, fp16
__device__ float  g_as1[NNODES];
__device__ float  g_ad1[NNODES];
__device__ float  g_ws0[D_IN * 2];       // W0 @ a_src0   [k][h]
__device__ float  g_wd0[D_IN * 2];       // W0 @ a_dst0   [k][h]

__device__ __forceinline__ float warpSum(float v) {
#pragma unroll
    for (int o = 16; o; o >>= 1) v += __shfl_xor_sync(0xffffffffu, v, o);
    return v;
}

__device__ __forceinline__ float lrelu(float e) {
    return e > 0.f ? e : NEG_SLOPE * e;
}

// ---------------- CSR: count -------------------------------------------------
__global__ void k_count(const int* __restrict__ ei) {
    int i = blockIdx.x * blockDim.x + threadIdx.x;
    if (i >= EALL) return;
    int d = (i < NEDGES) ? ei[NEDGES + i] : (i - NEDGES);
    atomicAdd(&g_deg[d], 1);
}

// Atomic segment assignment (order-independent); block OFFB additionally
// precomputes ws0/wd0 = W0 @ a_{src,dst}0.
__global__ void k_offsets(const float* __restrict__ W0,
                          const float* __restrict__ as0,
                          const float* __restrict__ ad0) {
    int b = blockIdx.x, tid = threadIdx.x;
    if (b < OFFB) {
        int i = b * 256 + tid;
        if (i >= NNODES) return;
        int d = g_deg[i];
        int o = atomicAdd(&g_deg[NNODES], d);
        g_off[i] = o;
        g_cursor[i] = o;
    } else if (tid < 192) {
        int idx = tid % 96, which = tid / 96;       // 96 = D_IN*2
        int k = idx >> 1, h = idx & 1;
        const float* a = which ? ad0 : as0;
        float s = 0.f;
#pragma unroll
        for (int c = 0; c < 64; c++)
            s = fmaf(W0[k * 128 + h * 64 + c], a[h * 64 + c], s);
        if (which) g_wd0[idx] = s; else g_ws0[idx] = s;
    }
}

// ---------------- fused: transform0 (blocks < T0B)  ||  CSR fill -------------
__global__ void __launch_bounds__(128) k_t0_fill(
        const int* __restrict__ ei,
        const float* __restrict__ x,
        const float* __restrict__ emb,
        const float* __restrict__ W0) {
    if (blockIdx.x >= T0B) {             // ---- fill branch ----
        int i = (blockIdx.x - T0B) * 128 + threadIdx.x;
        if (i >= EALL) return;
        int s, d;
        if (i < NEDGES) { s = ei[i]; d = ei[NEDGES + i]; }
        else            { s = i - NEDGES; d = s; }
        int p = atomicAdd(&g_cursor[d], 1);
        g_csrc[p] = s;
        return;
    }
    // ---- transform0 branch ----
    __shared__ float sfeat[NB0][D_IN];   // [node-in-tile][k]
    int j = threadIdx.x;
    int base = blockIdx.x * NB0;

    for (int idx = j; idx < NB0 * D_IN; idx += 128) {
        int nn = idx / D_IN, k = idx - nn * D_IN;
        int node = base + nn;
        if (node < NNODES) {
            float v;
            if (k < F_IN) v = x[node * XCOLS + k];
            else {
                int cid = (int)x[node * XCOLS + F_IN];
                v = emb[cid * CELL_DIM + (k - F_IN)];
            }
            sfeat[nn][k] = v;
        }
    }

    float w[D_IN];
#pragma unroll
    for (int k = 0; k < D_IN; k++) w[k] = W0[k * 128 + j];
    __syncthreads();

    float acc[NB0];
#pragma unroll
    for (int nn = 0; nn < NB0; nn++) acc[nn] = 0.f;
#pragma unroll
    for (int k = 0; k < D_IN; k++) {
        acc[0] = fmaf(sfeat[0][k], w[k], acc[0]);
        acc[1] = fmaf(sfeat[1][k], w[k], acc[1]);
        acc[2] = fmaf(sfeat[2][k], w[k], acc[2]);
        acc[3] = fmaf(sfeat[3][k], w[k], acc[3]);
        acc[4] = fmaf(sfeat[4][k], w[k], acc[4]);
        acc[5] = fmaf(sfeat[5][k], w[k], acc[5]);
        acc[6] = fmaf(sfeat[6][k], w[k], acc[6]);
        acc[7] = fmaf(sfeat[7][k], w[k], acc[7]);
    }
#pragma unroll
    for (int nn = 0; nn < NB0; nn++) {
        int node = base + nn;
        if (node < NNODES) g_h0[node * 128 + j] = __float2half_rn(acc[nn]);
    }
    // logits: 16 threads, one (node, head) each; fp32 throughout
    if (j < 2 * NB0) {
        int nn = j >> 1, h = j & 1;
        int node = base + nn;
        float as = 0.f, ad = 0.f;
#pragma unroll
        for (int k = 0; k < D_IN; k++) {
            float f = sfeat[nn][k];
            as = fmaf(f, g_ws0[k * 2 + h], as);
            ad = fmaf(f, g_wd0[k * 2 + h], ad);
        }
        if (node < NNODES) {
            g_as0[node * 2 + h] = as;
            g_ad0[node * 2 + h] = ad;
        }
    }
}

// ---------------- layer0 aggregation + LN/ELU + fused layer1 transform -------
// One warp per dst node, 8 warps/block. Lane L owns channels 4L..4L+3 of the
// 128-wide [head0|head1] row. h0 gathered as fp16 (8B/lane), 2 chains.
__global__ void __launch_bounds__(256) k_agg0(
        const float* __restrict__ b0,
        const float* __restrict__ lng,
        const float* __restrict__ lnb,
        const float* __restrict__ W1,
        const float* __restrict__ a_s1,
        const float* __restrict__ a_d1) {
    __shared__ float sW1[64 * 64];       // 16 KB
    __shared__ float sa1[64], sd1[64];
    __shared__ float sy[8][64];
    int tid = threadIdx.x;
    for (int i = tid; i < 4096; i += 256) sW1[i] = W1[i];
    if (tid < 64) { sa1[tid] = a_s1[tid]; sd1[tid] = a_d1[tid]; }
    __syncthreads();

    int warp = tid >> 5, lane = tid & 31;
    int n = blockIdx.x * 8 + warp;
    if (n >= NNODES) return;

    const float2* as0v = (const float2*)g_as0;
    const float2 adv = ((const float2*)g_ad0)[n];
    int head = lane >> 4;
    int c4 = lane & 15;
    int p0 = g_off[n], p1 = p0 + g_deg[n];
    const uint2* h0v = (const uint2*)g_h0;      // 4 halves per lane

    float sP = 0.f, sQ = 0.f;
    float4 accP = make_float4(0.f, 0.f, 0.f, 0.f);
    float4 accQ = make_float4(0.f, 0.f, 0.f, 0.f);

    for (int base = p0; base < p1; base += 32) {
        int cnt = min(32, p1 - base);
        int srcs = (lane < cnt) ? g_csrc[base + lane] : 0;
        int k = 0;
        for (; k + 1 < cnt; k += 2) {
            int sa = __shfl_sync(0xffffffffu, srcs, k);
            int sb = __shfl_sync(0xffffffffu, srcs, k + 1);
            float2 asa = as0v[sa];
            float2 asb = as0v[sb];
            uint2 ra = h0v[sa * 32 + lane];
            uint2 rb = h0v[sb * 32 + lane];
            float pa = __expf(lrelu(head ? (asa.y + adv.y) : (asa.x + adv.x)));
            float pb = __expf(lrelu(head ? (asb.y + adv.y) : (asb.x + adv.x)));
            float2 a01 = __half22float2(*(const __half2*)&ra.x);
            float2 a23 = __half22float2(*(const __half2*)&ra.y);
            float2 b01 = __half22float2(*(const __half2*)&rb.x);
            float2 b23 = __half22float2(*(const __half2*)&rb.y);
            sP += pa; sQ += pb;
            accP.x = fmaf(pa, a01.x, accP.x);
            accP.y = fmaf(pa, a01.y, accP.y);
            accP.z = fmaf(pa, a23.x, accP.z);
            accP.w = fmaf(pa, a23.y, accP.w);
            accQ.x = fmaf(pb, b01.x, accQ.x);
            accQ.y = fmaf(pb, b01.y, accQ.y);
            accQ.z = fmaf(pb, b23.x, accQ.z);
            accQ.w = fmaf(pb, b23.y, accQ.w);
        }
        if (k < cnt) {
            int sa = __shfl_sync(0xffffffffu, srcs, k);
            float2 asa = as0v[sa];
            uint2 ra = h0v[sa * 32 + lane];
            float pa = __expf(lrelu(head ? (asa.y + adv.y) : (asa.x + adv.x)));
            float2 a01 = __half22float2(*(const __half2*)&ra.x);
            float2 a23 = __half22float2(*(const __half2*)&ra.y);
            sP += pa;
            accP.x = fmaf(pa, a01.x, accP.x);
            accP.y = fmaf(pa, a01.y, accP.y);
            accP.z = fmaf(pa, a23.x, accP.z);
            accP.w = fmaf(pa, a23.y, accP.w);
        }
    }
    float inv = 1.f / (sP + sQ);
    float4 r;
    r.x = (accP.x + accQ.x) * inv;
    r.y = (accP.y + accQ.y) * inv;
    r.z = (accP.z + accQ.z) * inv;
    r.w = (accP.w + accQ.w) * inv;

    // head mean across halves, + bias
    float4 o;
    o.x = __shfl_xor_sync(0xffffffffu, r.x, 16);
    o.y = __shfl_xor_sync(0xffffffffu, r.y, 16);
    o.z = __shfl_xor_sync(0xffffffffu, r.z, 16);
    o.w = __shfl_xor_sync(0xffffffffu, r.w, 16);
    float4 bv = ((const float4*)b0)[c4];
    float4 v;
    v.x = 0.5f * (r.x + o.x) + bv.x;
    v.y = 0.5f * (r.y + o.y) + bv.y;
    v.z = 0.5f * (r.z + o.z) + bv.z;
    v.w = 0.5f * (r.w + o.w) + bv.w;

    // LayerNorm (each channel appears twice across the warp)
    float mu = warpSum(v.x + v.y + v.z + v.w) * (1.f / 128.f);
    float4 d = make_float4(v.x - mu, v.y - mu, v.z - mu, v.w - mu);
    float var = warpSum(d.x * d.x + d.y * d.y + d.z * d.z + d.w * d.w) * (1.f / 128.f);
    float rsv = rsqrtf(var + 1e-5f);
    float4 gv = ((const float4*)lng)[c4];
    float4 bb = ((const float4*)lnb)[c4];
    float4 y;
    y.x = d.x * rsv * gv.x + bb.x;
    y.y = d.y * rsv * gv.y + bb.y;
    y.z = d.z * rsv * gv.z + bb.z;
    y.w = d.w * rsv * gv.w + bb.w;
    // ELU via fast exp (abs err ~1e-7 vs expm1)
    y.x = y.x > 0.f ? y.x : (__expf(y.x) - 1.f);
    y.y = y.y > 0.f ? y.y : (__expf(y.y) - 1.f);
    y.z = y.z > 0.f ? y.z : (__expf(y.z) - 1.f);
    y.w = y.w > 0.f ? y.w : (__expf(y.w) - 1.f);

    // stage y[64] for this warp's node
    if (lane < 16) ((float4*)sy[warp])[c4] = y;
    __syncwarp();

    // fused layer1 transform: h1 = y @ W1; lane computes columns 2L, 2L+1
    float a0 = 0.f, a1 = 0.f;
#pragma unroll
    for (int k4 = 0; k4 < 16; k4++) {
        float4 y4 = ((const float4*)sy[warp])[k4];
        float2 w0 = ((const float2*)(sW1 + (4 * k4 + 0) * 64))[lane];
        float2 w1 = ((const float2*)(sW1 + (4 * k4 + 1) * 64))[lane];
        float2 w2 = ((const float2*)(sW1 + (4 * k4 + 2) * 64))[lane];
        float2 w3 = ((const float2*)(sW1 + (4 * k4 + 3) * 64))[lane];
        a0 = fmaf(y4.x, w0.x, a0); a1 = fmaf(y4.x, w0.y, a1);
        a0 = fmaf(y4.y, w1.x, a0); a1 = fmaf(y4.y, w1.y, a1);
        a0 = fmaf(y4.z, w2.x, a0); a1 = fmaf(y4.z, w2.y, a1);
        a0 = fmaf(y4.w, w3.x, a0); a1 = fmaf(y4.w, w3.y, a1);
    }
    ((__half2*)g_h1)[n * 32 + lane] = __floats2half2_rn(a0, a1);
    float ts = warpSum(a0 * sa1[2 * lane] + a1 * sa1[2 * lane + 1]);
    float td = warpSum(a0 * sd1[2 * lane] + a1 * sd1[2 * lane + 1]);
    if (lane == 0) { g_as1[n] = ts; g_ad1[n] = td; }
}

// ---------------- layer1 aggregation -> output -------------------------------
// One warp per dst node, lane owns channels 2L..2L+1 (half2 gather), 2 chains.
__global__ void __launch_bounds__(256) k_agg1(const float* __restrict__ b1,
                                              float* __restrict__ out) {
    int tid = threadIdx.x;
    int warp = tid >> 5, lane = tid & 31;
    int n = blockIdx.x * 8 + warp;
    if (n >= NNODES) return;
    float add = g_ad1[n];
    int p0 = g_off[n], p1 = p0 + g_deg[n];
    const __half2* h1v = (const __half2*)g_h1;

    float sP = 0.f, sQ = 0.f;
    float2 accP = make_float2(0.f, 0.f);
    float2 accQ = make_float2(0.f, 0.f);

    for (int base = p0; base < p1; base += 32) {
        int cnt = min(32, p1 - base);
        int srcs = (lane < cnt) ? g_csrc[base + lane] : 0;
        int k = 0;
        for (; k + 1 < cnt; k += 2) {
            int sa = __shfl_sync(0xffffffffu, srcs, k);
            int sb = __shfl_sync(0xffffffffu, srcs, k + 1);
            float pa = __expf(lrelu(g_as1[sa] + add));
            float pb = __expf(lrelu(g_as1[sb] + add));
            float2 ha = __half22float2(h1v[sa * 32 + lane]);
            float2 hb = __half22float2(h1v[sb * 32 + lane]);
            sP += pa; sQ += pb;
            accP.x = fmaf(pa, ha.x, accP.x);
            accP.y = fmaf(pa, ha.y, accP.y);
            accQ.x = fmaf(pb, hb.x, accQ.x);
            accQ.y = fmaf(pb, hb.y, accQ.y);
        }
        if (k < cnt) {
            int sa = __shfl_sync(0xffffffffu, srcs, k);
            float pa = __expf(lrelu(g_as1[sa] + add));
            float2 ha = __half22float2(h1v[sa * 32 + lane]);
            sP += pa;
            accP.x = fmaf(pa, ha.x, accP.x);
            accP.y = fmaf(pa, ha.y, accP.y);
        }
    }
    float inv = 1.f / (sP + sQ);
    float2 bv = ((const float2*)b1)[lane];
    float2 o;
    o.x = (accP.x + accQ.x) * inv + bv.x;
    o.y = (accP.y + accQ.y) * inv + bv.y;
    ((float2*)(out + n * 64))[lane] = o;
}

// ---------------- launch -----------------------------------------------------
extern "C" void kernel_launch(void* const* d_in, const int* in_sizes, int n_in,
                              void* d_out, int out_size) {
    const float* x   = (const float*)d_in[0];
    const int*   ei  = (const int*)  d_in[1];
    const float* emb = (const float*)d_in[2];
    const float* W0  = (const float*)d_in[3];
    const float* as0 = (const float*)d_in[4];
    const float* ad0 = (const float*)d_in[5];
    const float* b0  = (const float*)d_in[6];
    const float* lng = (const float*)d_in[7];
    const float* lnb = (const float*)d_in[8];
    const float* W1  = (const float*)d_in[9];
    const float* as1 = (const float*)d_in[10];
    const float* ad1 = (const float*)d_in[11];
    const float* b1  = (const float*)d_in[12];
    float* out = (float*)d_out;

    void* degPtr = nullptr;
    cudaGetSymbolAddress(&degPtr, g_deg);
    cudaMemsetAsync(degPtr, 0, (NNODES + 1) * sizeof(int));

    k_count<<<(EALL + 255) / 256, 256>>>(ei);
    k_offsets<<<OFFB + 1, 256>>>(W0, as0, ad0);
    k_t0_fill<<<T0B + FILLB, 128>>>(ei, x, emb, W0);
    k_agg0<<<(NNODES + 7) / 8, 256>>>(b0, lng, lnb, W1, as1, ad1);
    k_agg1<<<(NNODES + 7) / 8, 256>>>(b1, out);
}